// round 9
// baseline (speedup 1.0000x reference)
#include <cuda_runtime.h>
#include <cuda_bf16.h>
#include <mma.h>
#include <math.h>
#include <stdint.h>

using namespace nvcuda;

#define Pn 7
#define Sn 4
#define SCALE 0.0625f
#define TRANS_STD 0.1f
#define Cc 128
#define DF 1024
#define Bb 2
#define Hh 160
#define Ww 160
#define Nroi 256
#define INF (Cc*Pn*Pn)   // 6272
#define HW (Hh*Ww)       // 25600

// ---------------- scratch ----------------
__device__ float g_dataT[Bb*HW*Cc];                 // (B,H,W,C)
__device__ __align__(16) __nv_bfloat16 g_xh[Nroi*INF];
__device__ __align__(16) __nv_bfloat16 g_xl[Nroi*INF];
__device__ __align__(16) __nv_bfloat16 g_Wt1h[2*DF*INF];   // [2048][6272] = w1^T | wm1^T (hi)
__device__ __align__(16) __nv_bfloat16 g_Wt1l[2*DF*INF];   // lo
__device__ __align__(16) __nv_bfloat16 g_Wt2h[DF*DF];      // w2^T hi
__device__ __align__(16) __nv_bfloat16 g_Wt2l[DF*DF];      // w2^T lo
__device__ float g_part[3145728];                   // partials (6*256*2048 = 12*256*1024)
__device__ __align__(16) __nv_bfloat16 g_h1h[Nroi*DF];
__device__ __align__(16) __nv_bfloat16 g_h1l[Nroi*DF];
__device__ float g_m1[Nroi*DF];
__device__ float g_h2[Nroi*DF];
__device__ float g_off[Nroi*2*Pn*Pn];
__device__ float g_mask[Nroi*Pn*Pn];

__device__ __forceinline__ uint32_t smem_u32(const void* p) {
    uint32_t a;
    asm("{ .reg .u64 t; cvta.to.shared.u64 t, %1; cvt.u32.u64 %0, t; }" : "=r"(a) : "l"(p));
    return a;
}

// ---------------- transpose (B,C,H,W) -> (B,H,W,C) ----------------
__global__ void transpose_kernel(const float* __restrict__ in) {
    __shared__ float tile[32][33];
    int b  = blockIdx.z;
    int p0 = blockIdx.x * 32;
    int c0 = blockIdx.y * 32;
    int tx = threadIdx.x, ty = threadIdx.y;
    const float* src = in + (size_t)b * Cc * HW;
    float* dst = g_dataT + (size_t)b * HW * Cc;
    #pragma unroll
    for (int i = 0; i < 4; i++)
        tile[ty + 8*i][tx] = src[(c0 + ty + 8*i) * HW + p0 + tx];
    __syncthreads();
    #pragma unroll
    for (int i = 0; i < 4; i++)
        dst[(p0 + ty + 8*i) * Cc + c0 + tx] = tile[tx][ty + 8*i];
}

// ---------------- weight transpose + bf16 hi/lo split ----------------
__global__ void transW_kernel(const float* __restrict__ w_a, const float* __restrict__ w_b,
                              __nv_bfloat16* __restrict__ Wth,
                              __nv_bfloat16* __restrict__ Wtl,
                              int ldt, int two) {
    __shared__ float tile[32][33];
    const float* w = (two && blockIdx.z) ? w_b : w_a;
    int nOff = (two && blockIdx.z) ? DF : 0;
    int k0 = blockIdx.x * 32;
    int n0 = blockIdx.y * 32;
    int tx = threadIdx.x, ty = threadIdx.y;
    #pragma unroll
    for (int i = 0; i < 4; i++)
        tile[ty + 8*i][tx] = w[(size_t)(k0 + ty + 8*i) * DF + n0 + tx];
    __syncthreads();
    #pragma unroll
    for (int i = 0; i < 4; i++) {
        float v = tile[tx][ty + 8*i];
        __nv_bfloat16 hi = __float2bfloat16(v);
        __nv_bfloat16 lo = __float2bfloat16(v - __bfloat162float(hi));
        size_t o = (size_t)(nOff + n0 + ty + 8*i) * ldt + k0 + tx;
        Wth[o] = hi;
        Wtl[o] = lo;
    }
}

// ---------------- deformable RoI pool (two-phase, float4 channels) ----------------
// 128 threads = 4 warps; warp w handles unit (n*7+ph) = blockIdx.x*4 + w.
// Phase 1: 448 samples (4 units x 7 pw x 16 sub) computed by 128 threads.
// Phase 2: lane l covers channels 4l..4l+3 with float4 gathers.
template<bool TRANS>
__global__ __launch_bounds__(128) void pool_kernel(
    const float* __restrict__ rois,
    const float* __restrict__ trans,
    const float* __restrict__ mask,
    float* __restrict__ out)
{
    __shared__ int4   s_o[4][112];
    __shared__ float4 s_w[4][112];
    __shared__ int    s_cnt[4][Pn];
    __shared__ int    s_base[4];

    int tid = threadIdx.x;
    int u0 = blockIdx.x * 4;

    if (tid < 4 * Pn) s_cnt[tid / Pn][tid % Pn] = 0;
    __syncthreads();

    #pragma unroll
    for (int it = 0; it < 4; it++) {
        int idx = it * 128 + tid;         // 0..511; need 448
        if (idx < 448) {
            int ul     = idx / 112;
            int within = idx - ul * 112;
            int pw = within >> 4;
            int s  = within & 15;
            int ih = s >> 2;
            int iw = s & 3;
            int unit = u0 + ul;
            int n  = unit / Pn;
            int ph = unit - n * Pn;

            const float* r = rois + n * 5;
            int   bi = (int)r[0];
            float x1 = rintf(r[1]) * SCALE - 0.5f;
            float y1 = rintf(r[2]) * SCALE - 0.5f;
            float x2 = (rintf(r[3]) + 1.0f) * SCALE - 0.5f;
            float y2 = (rintf(r[4]) + 1.0f) * SCALE - 0.5f;
            float roi_w = fmaxf(x2 - x1, 0.1f);
            float roi_h = fmaxf(y2 - y1, 0.1f);
            float bin_w = roi_w / (float)Pn;
            float bin_h = roi_h / (float)Pn;
            float sub_w = bin_w / (float)Sn;
            float sub_h = bin_h / (float)Sn;

            float tx = 0.f, tyv = 0.f;
            if (TRANS) {
                tx  = trans[n*98 +      ph*7 + pw] * TRANS_STD;
                tyv = trans[n*98 + 49 + ph*7 + pw] * TRANS_STD;
            }
            float wv = (float)pw * bin_w + x1 + tx  * roi_w + (float)iw * sub_w;
            float hv = (float)ph * bin_h + y1 + tyv * roi_h + (float)ih * sub_h;

            int4   o4 = make_int4(0, 0, 0, 0);
            float4 w4 = make_float4(0.f, 0.f, 0.f, 0.f);
            bool valid = !(wv < -0.5f || wv > (float)Ww - 0.5f ||
                           hv < -0.5f || hv > (float)Hh - 0.5f);
            if (valid) {
                float wc = fminf(fmaxf(wv, 0.f), (float)Ww - 1.f);
                float hc = fminf(fmaxf(hv, 0.f), (float)Hh - 1.f);
                int x0 = (int)floorf(wc);
                int y0 = (int)floorf(hc);
                int x1i = min(x0 + 1, Ww - 1);
                int y1i = min(y0 + 1, Hh - 1);
                float lx = wc - (float)x0;
                float ly = hc - (float)y0;
                o4.x = (y0 * Ww + x0) * Cc;
                o4.y = (x1i - x0) * Cc;
                o4.z = (y1i - y0) * Ww * Cc;
                w4 = make_float4((1.f-ly)*(1.f-lx), (1.f-ly)*lx, ly*(1.f-lx), ly*lx);
                atomicAdd(&s_cnt[ul][pw], 1);
            }
            s_o[ul][within] = o4;
            s_w[ul][within] = w4;
            if (within == 0) s_base[ul] = bi * HW * Cc;
        }
    }
    __syncthreads();

    int wid = tid >> 5;
    int l   = tid & 31;
    int unit = u0 + wid;
    int n  = unit / Pn;
    int ph = unit - n * Pn;
    const float* base = g_dataT + s_base[wid];
    int c4 = l * 4;

    #pragma unroll
    for (int pw = 0; pw < Pn; pw++) {
        float4 acc = make_float4(0.f, 0.f, 0.f, 0.f);
        #pragma unroll 4
        for (int s = 0; s < 16; s++) {
            int4   o = s_o[wid][pw*16 + s];
            float4 w = s_w[wid][pw*16 + s];
            const float* p = base + o.x + c4;
            float4 v00 = *(const float4*)(p);
            float4 v01 = *(const float4*)(p + o.y);
            float4 v10 = *(const float4*)(p + o.z);
            float4 v11 = *(const float4*)(p + o.y + o.z);
            acc.x += v00.x*w.x + v01.x*w.y + v10.x*w.z + v11.x*w.w;
            acc.y += v00.y*w.x + v01.y*w.y + v10.y*w.z + v11.y*w.w;
            acc.z += v00.z*w.x + v01.z*w.y + v10.z*w.z + v11.z*w.w;
            acc.w += v00.w*w.x + v01.w*w.y + v10.w*w.z + v11.w*w.w;
        }
        int cnt = s_cnt[wid][pw];
        float a[4] = {acc.x, acc.y, acc.z, acc.w};
        float mk = TRANS ? mask[n*49 + ph*7 + pw] : 0.f;
        #pragma unroll
        for (int j = 0; j < 4; j++) {
            float res = (cnt > 0) ? a[j] / (float)cnt : 0.f;
            int oidx = n*INF + (c4 + j)*49 + ph*7 + pw;
            if (TRANS) {
                out[oidx] = res * mk;
            } else {
                __nv_bfloat16 hi = __float2bfloat16(res);
                g_xh[oidx] = hi;
                g_xl[oidx] = __float2bfloat16(res - __bfloat162float(hi));
            }
        }
    }
}

// ---------------- WMMA bf16 GEMM, cp.async 2-stage, KS=64 ----------------
// grid: x = Ntiles, y = Mtiles, z = term*kchunks + kc
//   term 0: Ah@Bh   term 1: Ah@Bl   term 2: Al@Bh
#define KS 64
#define SPAD 72
#define NSTG 2
#define STG_ELEMS (2 * 128 * SPAD)     // A + B per stage (bf16 elems)
__global__ __launch_bounds__(256) void gemm_wmma(
    const __nv_bfloat16* __restrict__ Ah, const __nv_bfloat16* __restrict__ Al, int lda,
    const __nv_bfloat16* __restrict__ Bh, const __nv_bfloat16* __restrict__ Bl, int ldb,
    float* __restrict__ part, int Kper, int kchunks, int Nfull)
{
    extern __shared__ __nv_bfloat16 smem[];

    int tid = threadIdx.x;
    int wid = tid >> 5;
    int wm = wid & 3;       // 0..3 : M position (32 rows each)
    int wn = wid >> 2;      // 0..1 : N position (64 cols each)

    int z = blockIdx.z;
    int term = z / kchunks;
    int kc   = z % kchunks;
    const __nv_bfloat16* A = (term == 2) ? Al : Ah;
    const __nv_bfloat16* B = (term == 1) ? Bl : Bh;

    int m0 = blockIdx.y * 128;
    int n0 = blockIdx.x * 128;
    const __nv_bfloat16* Abase = A + (size_t)m0 * lda + (size_t)kc * Kper;
    const __nv_bfloat16* Bbase = B + (size_t)n0 * ldb + (size_t)kc * Kper;

    wmma::fragment<wmma::accumulator, 16, 16, 16, float> acc[2][4];
    #pragma unroll
    for (int i = 0; i < 2; i++)
        #pragma unroll
        for (int j = 0; j < 4; j++) wmma::fill_fragment(acc[i][j], 0.0f);

    int stages = Kper / KS;
    int r  = tid >> 3;       // row group
    int ch = tid & 7;        // 16B chunk within 128B row

    auto issue = [&](int s) {
        int buf = s % NSTG;
        __nv_bfloat16* dA = smem + buf * STG_ELEMS;
        __nv_bfloat16* dB = dA + 128 * SPAD;
        const __nv_bfloat16* a = Abase + s * KS;
        const __nv_bfloat16* b = Bbase + s * KS;
        #pragma unroll
        for (int i = 0; i < 4; i++) {
            int rr = i * 32 + r;
            uint32_t da = smem_u32(dA + rr * SPAD + ch * 8);
            asm volatile("cp.async.cg.shared.global [%0], [%1], 16;"
                         :: "r"(da), "l"(a + (size_t)rr * lda + ch * 8));
            uint32_t db = smem_u32(dB + rr * SPAD + ch * 8);
            asm volatile("cp.async.cg.shared.global [%0], [%1], 16;"
                         :: "r"(db), "l"(b + (size_t)rr * ldb + ch * 8));
        }
        asm volatile("cp.async.commit_group;");
    };

    #pragma unroll
    for (int i = 0; i < NSTG - 1; i++) {
        if (i < stages) issue(i);
        else asm volatile("cp.async.commit_group;");
    }

    for (int s = 0; s < stages; s++) {
        if (s + NSTG - 1 < stages) issue(s + NSTG - 1);
        else asm volatile("cp.async.commit_group;");

        asm volatile("cp.async.wait_group %0;" :: "n"(NSTG - 1));
        __syncthreads();

        int buf = s % NSTG;
        const __nv_bfloat16* cA = smem + buf * STG_ELEMS;
        const __nv_bfloat16* cB = cA + 128 * SPAD;
        #pragma unroll
        for (int kk = 0; kk < KS; kk += 16) {
            wmma::fragment<wmma::matrix_a, 16, 16, 16, __nv_bfloat16, wmma::row_major> af[2];
            wmma::fragment<wmma::matrix_b, 16, 16, 16, __nv_bfloat16, wmma::col_major> bfr[4];
            #pragma unroll
            for (int i = 0; i < 2; i++)
                wmma::load_matrix_sync(af[i], cA + (wm * 32 + i * 16) * SPAD + kk, SPAD);
            #pragma unroll
            for (int j = 0; j < 4; j++)
                wmma::load_matrix_sync(bfr[j], cB + (wn * 64 + j * 16) * SPAD + kk, SPAD);
            #pragma unroll
            for (int i = 0; i < 2; i++)
                #pragma unroll
                for (int j = 0; j < 4; j++)
                    wmma::mma_sync(acc[i][j], af[i], bfr[j], acc[i][j]);
        }
        __syncthreads();
    }

    float* outp = part + ((size_t)z * Nroi + m0) * Nfull + n0;
    #pragma unroll
    for (int i = 0; i < 2; i++)
        #pragma unroll
        for (int j = 0; j < 4; j++)
            wmma::store_matrix_sync(outp + (size_t)(wm * 32 + i * 16) * Nfull + wn * 64 + j * 16,
                                    acc[i][j], Nfull, wmma::mem_row_major);
}

// ---------------- reduce 1: sum 6 slices [256][2048]; split h (bf16 hi/lo) / m (fp32)
__global__ void reduce1_kernel(const float* __restrict__ b1, const float* __restrict__ bm1) {
    int i = blockIdx.x * 256 + threadIdx.x;   // over 256*2048
    int m = i >> 11;
    int n = i & 2047;
    float s = (n < DF) ? b1[n] : bm1[n - DF];
    #pragma unroll
    for (int zz = 0; zz < 6; zz++) s += g_part[(size_t)zz * (Nroi*2*DF) + i];
    s = fmaxf(s, 0.f);
    if (n < DF) {
        __nv_bfloat16 hi = __float2bfloat16(s);
        g_h1h[m*DF + n] = hi;
        g_h1l[m*DF + n] = __float2bfloat16(s - __bfloat162float(hi));
    } else {
        g_m1[m*DF + n - DF] = s;
    }
}

// ---------------- reduce 2: sum 12 slices [256][1024] + b2, relu -> h2 fp32
__global__ void reduce2_kernel(const float* __restrict__ b2) {
    int i = blockIdx.x * 256 + threadIdx.x;
    int n = i & (DF - 1);
    float s = b2[n];
    #pragma unroll
    for (int zz = 0; zz < 12; zz++) s += g_part[(size_t)zz * (Nroi*DF) + i];
    g_h2[i] = fmaxf(s, 0.f);
}

// ---------------- small GEMM: (256,1024) @ (1024,Ncols) + bias [, sigmoid] -------
__global__ __launch_bounds__(128) void gemm_small(
    const float* __restrict__ A, const float* __restrict__ Wt,
    const float* __restrict__ bias, float* __restrict__ out,
    int Ncols, int act)
{
    __shared__ float arow[8][DF];
    int tid = threadIdx.x;
    int m0 = blockIdx.x * 8;
    #pragma unroll
    for (int g = 0; g < 8; g++)
        for (int k = tid; k < DF; k += 128)
            arow[g][k] = A[(size_t)(m0 + g) * DF + k];
    __syncthreads();

    if (tid < Ncols) {
        float bv = bias[tid];
        float acc[8];
        #pragma unroll
        for (int g = 0; g < 8; g++) acc[g] = bv;
        for (int k = 0; k < DF; k += 4) {
            float w0 = Wt[(size_t)(k + 0) * Ncols + tid];
            float w1 = Wt[(size_t)(k + 1) * Ncols + tid];
            float w2 = Wt[(size_t)(k + 2) * Ncols + tid];
            float w3 = Wt[(size_t)(k + 3) * Ncols + tid];
            #pragma unroll
            for (int g = 0; g < 8; g++) {
                float4 av = *(const float4*)&arow[g][k];
                acc[g] += av.x * w0 + av.y * w1 + av.z * w2 + av.w * w3;
            }
        }
        #pragma unroll
        for (int g = 0; g < 8; g++) {
            float v = acc[g];
            if (act) v = 1.f / (1.f + expf(-v));
            out[(size_t)(m0 + g) * Ncols + tid] = v;
        }
    }
}

// ---------------- launch ----------------
extern "C" void kernel_launch(void* const* d_in, const int* in_sizes, int n_in,
                              void* d_out, int out_size) {
    const float* data = (const float*)d_in[0];
    const float* rois = (const float*)d_in[1];
    const float* w1   = (const float*)d_in[2];
    const float* b1   = (const float*)d_in[3];
    const float* w2   = (const float*)d_in[4];
    const float* b2   = (const float*)d_in[5];
    const float* w3   = (const float*)d_in[6];
    const float* b3   = (const float*)d_in[7];
    const float* wm1  = (const float*)d_in[8];
    const float* bm1  = (const float*)d_in[9];
    const float* wm2  = (const float*)d_in[10];
    const float* bm2  = (const float*)d_in[11];
    float* out = (float*)d_out;

    float *p_part, *p_m1, *p_h2, *p_off, *p_mask;
    __nv_bfloat16 *p_xh, *p_xl, *p_W1h, *p_W1l, *p_W2h, *p_W2l, *p_h1h, *p_h1l;
    cudaGetSymbolAddress((void**)&p_part, g_part);
    cudaGetSymbolAddress((void**)&p_m1,   g_m1);
    cudaGetSymbolAddress((void**)&p_h2,   g_h2);
    cudaGetSymbolAddress((void**)&p_off,  g_off);
    cudaGetSymbolAddress((void**)&p_mask, g_mask);
    cudaGetSymbolAddress((void**)&p_xh,   g_xh);
    cudaGetSymbolAddress((void**)&p_xl,   g_xl);
    cudaGetSymbolAddress((void**)&p_W1h,  g_Wt1h);
    cudaGetSymbolAddress((void**)&p_W1l,  g_Wt1l);
    cudaGetSymbolAddress((void**)&p_W2h,  g_Wt2h);
    cudaGetSymbolAddress((void**)&p_W2l,  g_Wt2l);
    cudaGetSymbolAddress((void**)&p_h1h,  g_h1h);
    cudaGetSymbolAddress((void**)&p_h1l,  g_h1l);

    static int attr_set = 0;
    if (!attr_set) {
        cudaFuncSetAttribute(gemm_wmma, cudaFuncAttributeMaxDynamicSharedMemorySize,
                             NSTG * STG_ELEMS * 2);
        attr_set = 1;
    }
    const int smem_bytes = NSTG * STG_ELEMS * 2;   // 73728

    // idx 0: transpose data to channel-last
    transpose_kernel<<<dim3(HW/32, Cc/32, Bb), dim3(32, 8)>>>(data);

    // idx 1: weight transpose + split for w1 & wm1 (merged)
    transW_kernel<<<dim3(INF/32, DF/32, 2), dim3(32, 8)>>>(w1, wm1, p_W1h, p_W1l, INF, 1);

    // idx 2: pool1 -> xh/xl bf16
    pool_kernel<false><<<dim3(Nroi*Pn/4), 128>>>(rois, nullptr, nullptr, nullptr);

    // idx 3 (ncu capture slot): gemm1 [256x6272]@[6272x2048], 3 terms x splitK2 -> 6 slices
    gemm_wmma<<<dim3(16, 2, 6), 256, smem_bytes>>>(p_xh, p_xl, INF, p_W1h, p_W1l, INF,
                                                   p_part, INF/2, 2, 2*DF);

    // idx 4: weight transpose + split for w2
    transW_kernel<<<dim3(DF/32, DF/32, 1), dim3(32, 8)>>>(w2, nullptr, p_W2h, p_W2l, DF, 0);

    // idx 5: reduce -> h1 (bf16 hi/lo) and m1 (fp32)
    reduce1_kernel<<<(Nroi*2*DF)/256, 256>>>(b1, bm1);

    // idx 6: gemm2 [256x1024]@[1024x1024], 3 terms x splitK4 -> 12 slices
    gemm_wmma<<<dim3(8, 2, 12), 256, smem_bytes>>>(p_h1h, p_h1l, DF, p_W2h, p_W2l, DF,
                                                   p_part, DF/4, 4, DF);

    // idx 7: reduce -> h2 fp32
    reduce2_kernel<<<(Nroi*DF)/256, 256>>>(b2);

    // idx 8/9: offsets & mask heads
    gemm_small<<<Nroi/8, 128>>>(p_h2, w3, b3, p_off, 2*Pn*Pn, 0);
    gemm_small<<<Nroi/8, 128>>>(p_m1, wm2, bm2, p_mask, Pn*Pn, 1);

    // idx 10: pool2 with offsets, multiply mask -> out
    pool_kernel<true><<<dim3(Nroi*Pn/4), 128>>>(rois, p_off, p_mask, out);
}

// round 11
// speedup vs baseline: 1.0482x; 1.0482x over previous
#include <cuda_runtime.h>
#include <cuda_bf16.h>
#include <mma.h>
#include <math.h>
#include <stdint.h>

using namespace nvcuda;

#define Pn 7
#define Sn 4
#define SCALE 0.0625f
#define TRANS_STD 0.1f
#define Cc 128
#define DF 1024
#define Bb 2
#define Hh 160
#define Ww 160
#define Nroi 256
#define INF (Cc*Pn*Pn)   // 6272
#define HW (Hh*Ww)       // 25600

// ---------------- scratch ----------------
__device__ float g_dataT[Bb*HW*Cc];                 // (B,H,W,C)
__device__ __align__(16) __nv_bfloat16 g_xh[Nroi*INF];
__device__ __align__(16) __nv_bfloat16 g_xl[Nroi*INF];
__device__ __align__(16) __nv_bfloat16 g_Wt1h[2*DF*INF];   // [2048][6272] = w1^T | wm1^T (hi)
__device__ __align__(16) __nv_bfloat16 g_Wt1l[2*DF*INF];   // lo
__device__ __align__(16) __nv_bfloat16 g_Wt2h[DF*DF];      // w2^T hi
__device__ __align__(16) __nv_bfloat16 g_Wt2l[DF*DF];      // w2^T lo
__device__ float g_part[11010048];                  // partials (21*256*2048)
__device__ __align__(16) __nv_bfloat16 g_h1h[Nroi*DF];
__device__ __align__(16) __nv_bfloat16 g_h1l[Nroi*DF];
__device__ float g_m1[Nroi*DF];
__device__ float g_h2[Nroi*DF];
__device__ float g_off[Nroi*2*Pn*Pn];
__device__ float g_mask[Nroi*Pn*Pn];

__device__ __forceinline__ uint32_t smem_u32(const void* p) {
    uint32_t a;
    asm("{ .reg .u64 t; cvta.to.shared.u64 t, %1; cvt.u32.u64 %0, t; }" : "=r"(a) : "l"(p));
    return a;
}

// ---------------- transpose (B,C,H,W) -> (B,H,W,C) ----------------
__global__ void transpose_kernel(const float* __restrict__ in) {
    __shared__ float tile[32][33];
    int b  = blockIdx.z;
    int p0 = blockIdx.x * 32;
    int c0 = blockIdx.y * 32;
    int tx = threadIdx.x, ty = threadIdx.y;
    const float* src = in + (size_t)b * Cc * HW;
    float* dst = g_dataT + (size_t)b * HW * Cc;
    #pragma unroll
    for (int i = 0; i < 4; i++)
        tile[ty + 8*i][tx] = src[(c0 + ty + 8*i) * HW + p0 + tx];
    __syncthreads();
    #pragma unroll
    for (int i = 0; i < 4; i++)
        dst[(p0 + ty + 8*i) * Cc + c0 + tx] = tile[tx][ty + 8*i];
}

// ---------------- weight transpose + bf16 hi/lo split ----------------
__global__ void transW_kernel(const float* __restrict__ w_a, const float* __restrict__ w_b,
                              __nv_bfloat16* __restrict__ Wth,
                              __nv_bfloat16* __restrict__ Wtl,
                              int ldt, int two) {
    __shared__ float tile[32][33];
    const float* w = (two && blockIdx.z) ? w_b : w_a;
    int nOff = (two && blockIdx.z) ? DF : 0;
    int k0 = blockIdx.x * 32;
    int n0 = blockIdx.y * 32;
    int tx = threadIdx.x, ty = threadIdx.y;
    #pragma unroll
    for (int i = 0; i < 4; i++)
        tile[ty + 8*i][tx] = w[(size_t)(k0 + ty + 8*i) * DF + n0 + tx];
    __syncthreads();
    #pragma unroll
    for (int i = 0; i < 4; i++) {
        float v = tile[tx][ty + 8*i];
        __nv_bfloat16 hi = __float2bfloat16(v);
        __nv_bfloat16 lo = __float2bfloat16(v - __bfloat162float(hi));
        size_t o = (size_t)(nOff + n0 + ty + 8*i) * ldt + k0 + tx;
        Wth[o] = hi;
        Wtl[o] = lo;
    }
}

// ---------------- deformable RoI pool (two-phase, float4 channels) ----------------
// 128 threads = 4 warps; warp w handles unit (n*7+ph) = blockIdx.x*4 + w.
// Phase 1: 448 samples (4 units x 7 pw x 16 sub) computed by 128 threads.
// Phase 2: lane l covers channels 4l..4l+3 with float4 gathers.
template<bool TRANS>
__global__ __launch_bounds__(128) void pool_kernel(
    const float* __restrict__ rois,
    const float* __restrict__ trans,
    const float* __restrict__ mask,
    float* __restrict__ out)
{
    __shared__ int4   s_o[4][112];
    __shared__ float4 s_w[4][112];
    __shared__ int    s_cnt[4][Pn];
    __shared__ int    s_base[4];

    int tid = threadIdx.x;
    int u0 = blockIdx.x * 4;

    if (tid < 4 * Pn) s_cnt[tid / Pn][tid % Pn] = 0;
    __syncthreads();

    #pragma unroll
    for (int it = 0; it < 4; it++) {
        int idx = it * 128 + tid;         // 0..511; need 448
        if (idx < 448) {
            int ul     = idx / 112;
            int within = idx - ul * 112;
            int pw = within >> 4;
            int s  = within & 15;
            int ih = s >> 2;
            int iw = s & 3;
            int unit = u0 + ul;
            int n  = unit / Pn;
            int ph = unit - n * Pn;

            const float* r = rois + n * 5;
            int   bi = (int)r[0];
            float x1 = rintf(r[1]) * SCALE - 0.5f;
            float y1 = rintf(r[2]) * SCALE - 0.5f;
            float x2 = (rintf(r[3]) + 1.0f) * SCALE - 0.5f;
            float y2 = (rintf(r[4]) + 1.0f) * SCALE - 0.5f;
            float roi_w = fmaxf(x2 - x1, 0.1f);
            float roi_h = fmaxf(y2 - y1, 0.1f);
            float bin_w = roi_w / (float)Pn;
            float bin_h = roi_h / (float)Pn;
            float sub_w = bin_w / (float)Sn;
            float sub_h = bin_h / (float)Sn;

            float tx = 0.f, tyv = 0.f;
            if (TRANS) {
                tx  = trans[n*98 +      ph*7 + pw] * TRANS_STD;
                tyv = trans[n*98 + 49 + ph*7 + pw] * TRANS_STD;
            }
            float wv = (float)pw * bin_w + x1 + tx  * roi_w + (float)iw * sub_w;
            float hv = (float)ph * bin_h + y1 + tyv * roi_h + (float)ih * sub_h;

            int4   o4 = make_int4(0, 0, 0, 0);
            float4 w4 = make_float4(0.f, 0.f, 0.f, 0.f);
            bool valid = !(wv < -0.5f || wv > (float)Ww - 0.5f ||
                           hv < -0.5f || hv > (float)Hh - 0.5f);
            if (valid) {
                float wc = fminf(fmaxf(wv, 0.f), (float)Ww - 1.f);
                float hc = fminf(fmaxf(hv, 0.f), (float)Hh - 1.f);
                int x0 = (int)floorf(wc);
                int y0 = (int)floorf(hc);
                int x1i = min(x0 + 1, Ww - 1);
                int y1i = min(y0 + 1, Hh - 1);
                float lx = wc - (float)x0;
                float ly = hc - (float)y0;
                o4.x = (y0 * Ww + x0) * Cc;
                o4.y = (x1i - x0) * Cc;
                o4.z = (y1i - y0) * Ww * Cc;
                w4 = make_float4((1.f-ly)*(1.f-lx), (1.f-ly)*lx, ly*(1.f-lx), ly*lx);
                atomicAdd(&s_cnt[ul][pw], 1);
            }
            s_o[ul][within] = o4;
            s_w[ul][within] = w4;
            if (within == 0) s_base[ul] = bi * HW * Cc;
        }
    }
    __syncthreads();

    int wid = tid >> 5;
    int l   = tid & 31;
    int unit = u0 + wid;
    int n  = unit / Pn;
    int ph = unit - n * Pn;
    const float* base = g_dataT + s_base[wid];
    int c4 = l * 4;

    #pragma unroll
    for (int pw = 0; pw < Pn; pw++) {
        float4 acc = make_float4(0.f, 0.f, 0.f, 0.f);
        #pragma unroll 4
        for (int s = 0; s < 16; s++) {
            int4   o = s_o[wid][pw*16 + s];
            float4 w = s_w[wid][pw*16 + s];
            const float* p = base + o.x + c4;
            float4 v00 = *(const float4*)(p);
            float4 v01 = *(const float4*)(p + o.y);
            float4 v10 = *(const float4*)(p + o.z);
            float4 v11 = *(const float4*)(p + o.y + o.z);
            acc.x += v00.x*w.x + v01.x*w.y + v10.x*w.z + v11.x*w.w;
            acc.y += v00.y*w.x + v01.y*w.y + v10.y*w.z + v11.y*w.w;
            acc.z += v00.z*w.x + v01.z*w.y + v10.z*w.z + v11.z*w.w;
            acc.w += v00.w*w.x + v01.w*w.y + v10.w*w.z + v11.w*w.w;
        }
        int cnt = s_cnt[wid][pw];
        float a[4] = {acc.x, acc.y, acc.z, acc.w};
        float mk = TRANS ? mask[n*49 + ph*7 + pw] : 0.f;
        #pragma unroll
        for (int j = 0; j < 4; j++) {
            float res = (cnt > 0) ? a[j] / (float)cnt : 0.f;
            int oidx = n*INF + (c4 + j)*49 + ph*7 + pw;
            if (TRANS) {
                out[oidx] = res * mk;
            } else {
                __nv_bfloat16 hi = __float2bfloat16(res);
                g_xh[oidx] = hi;
                g_xl[oidx] = __float2bfloat16(res - __bfloat162float(hi));
            }
        }
    }
}

// ---------------- WMMA bf16 GEMM, cp.async 2-stage, KS=64 ----------------
// grid: x = Ntiles, y = Mtiles, z = term*kchunks + kc
//   term 0: Ah@Bh   term 1: Ah@Bl   term 2: Al@Bh
#define KS 64
#define SPAD 72
#define NSTG 2
#define STG_ELEMS (2 * 128 * SPAD)     // A + B per stage (bf16 elems)
__global__ __launch_bounds__(256) void gemm_wmma(
    const __nv_bfloat16* __restrict__ Ah, const __nv_bfloat16* __restrict__ Al, int lda,
    const __nv_bfloat16* __restrict__ Bh, const __nv_bfloat16* __restrict__ Bl, int ldb,
    float* __restrict__ part, int Kper, int kchunks, int Nfull)
{
    extern __shared__ __nv_bfloat16 smem[];

    int tid = threadIdx.x;
    int wid = tid >> 5;
    int wm = wid & 3;       // 0..3 : M position (32 rows each)
    int wn = wid >> 2;      // 0..1 : N position (64 cols each)

    int z = blockIdx.z;
    int term = z / kchunks;
    int kc   = z % kchunks;
    const __nv_bfloat16* A = (term == 2) ? Al : Ah;
    const __nv_bfloat16* B = (term == 1) ? Bl : Bh;

    int m0 = blockIdx.y * 128;
    int n0 = blockIdx.x * 128;
    const __nv_bfloat16* Abase = A + (size_t)m0 * lda + (size_t)kc * Kper;
    const __nv_bfloat16* Bbase = B + (size_t)n0 * ldb + (size_t)kc * Kper;

    wmma::fragment<wmma::accumulator, 16, 16, 16, float> acc[2][4];
    #pragma unroll
    for (int i = 0; i < 2; i++)
        #pragma unroll
        for (int j = 0; j < 4; j++) wmma::fill_fragment(acc[i][j], 0.0f);

    int stages = Kper / KS;
    int r  = tid >> 3;       // row group
    int ch = tid & 7;        // 16B chunk within 128B row

    auto issue = [&](int s) {
        int buf = s % NSTG;
        __nv_bfloat16* dA = smem + buf * STG_ELEMS;
        __nv_bfloat16* dB = dA + 128 * SPAD;
        const __nv_bfloat16* a = Abase + s * KS;
        const __nv_bfloat16* b = Bbase + s * KS;
        #pragma unroll
        for (int i = 0; i < 4; i++) {
            int rr = i * 32 + r;
            uint32_t da = smem_u32(dA + rr * SPAD + ch * 8);
            asm volatile("cp.async.cg.shared.global [%0], [%1], 16;"
                         :: "r"(da), "l"(a + (size_t)rr * lda + ch * 8));
            uint32_t db = smem_u32(dB + rr * SPAD + ch * 8);
            asm volatile("cp.async.cg.shared.global [%0], [%1], 16;"
                         :: "r"(db), "l"(b + (size_t)rr * ldb + ch * 8));
        }
        asm volatile("cp.async.commit_group;");
    };

    #pragma unroll
    for (int i = 0; i < NSTG - 1; i++) {
        if (i < stages) issue(i);
        else asm volatile("cp.async.commit_group;");
    }

    for (int s = 0; s < stages; s++) {
        if (s + NSTG - 1 < stages) issue(s + NSTG - 1);
        else asm volatile("cp.async.commit_group;");

        asm volatile("cp.async.wait_group %0;" :: "n"(NSTG - 1));
        __syncthreads();

        int buf = s % NSTG;
        const __nv_bfloat16* cA = smem + buf * STG_ELEMS;
        const __nv_bfloat16* cB = cA + 128 * SPAD;
        #pragma unroll
        for (int kk = 0; kk < KS; kk += 16) {
            wmma::fragment<wmma::matrix_a, 16, 16, 16, __nv_bfloat16, wmma::row_major> af[2];
            wmma::fragment<wmma::matrix_b, 16, 16, 16, __nv_bfloat16, wmma::col_major> bfr[4];
            #pragma unroll
            for (int i = 0; i < 2; i++)
                wmma::load_matrix_sync(af[i], cA + (wm * 32 + i * 16) * SPAD + kk, SPAD);
            #pragma unroll
            for (int j = 0; j < 4; j++)
                wmma::load_matrix_sync(bfr[j], cB + (wn * 64 + j * 16) * SPAD + kk, SPAD);
            #pragma unroll
            for (int i = 0; i < 2; i++)
                #pragma unroll
                for (int j = 0; j < 4; j++)
                    wmma::mma_sync(acc[i][j], af[i], bfr[j], acc[i][j]);
        }
        __syncthreads();
    }

    float* outp = part + ((size_t)z * Nroi + m0) * Nfull + n0;
    #pragma unroll
    for (int i = 0; i < 2; i++)
        #pragma unroll
        for (int j = 0; j < 4; j++)
            wmma::store_matrix_sync(outp + (size_t)(wm * 32 + i * 16) * Nfull + wn * 64 + j * 16,
                                    acc[i][j], Nfull, wmma::mem_row_major);
}

// ---------------- reduce 1: sum 21 slices [256][2048]; split h (bf16 hi/lo) / m (fp32)
__global__ void reduce1_kernel(const float* __restrict__ b1, const float* __restrict__ bm1) {
    int i = blockIdx.x * 256 + threadIdx.x;   // over 256*2048
    int m = i >> 11;
    int n = i & 2047;
    float s = (n < DF) ? b1[n] : bm1[n - DF];
    #pragma unroll
    for (int zz = 0; zz < 21; zz++) s += g_part[(size_t)zz * (Nroi*2*DF) + i];
    s = fmaxf(s, 0.f);
    if (n < DF) {
        __nv_bfloat16 hi = __float2bfloat16(s);
        g_h1h[m*DF + n] = hi;
        g_h1l[m*DF + n] = __float2bfloat16(s - __bfloat162float(hi));
    } else {
        g_m1[m*DF + n - DF] = s;
    }
}

// ---------------- reduce 2: sum 24 slices [256][1024] + b2, relu -> h2 fp32
__global__ void reduce2_kernel(const float* __restrict__ b2) {
    int i = blockIdx.x * 256 + threadIdx.x;
    int n = i & (DF - 1);
    float s = b2[n];
    #pragma unroll
    for (int zz = 0; zz < 24; zz++) s += g_part[(size_t)zz * (Nroi*DF) + i];
    g_h2[i] = fmaxf(s, 0.f);
}

// ---------------- small GEMM: (256,1024) @ (1024,Ncols) + bias [, sigmoid] -------
__global__ __launch_bounds__(128) void gemm_small(
    const float* __restrict__ A, const float* __restrict__ Wt,
    const float* __restrict__ bias, float* __restrict__ out,
    int Ncols, int act)
{
    __shared__ float arow[8][DF];
    int tid = threadIdx.x;
    int m0 = blockIdx.x * 8;
    #pragma unroll
    for (int g = 0; g < 8; g++)
        for (int k = tid; k < DF; k += 128)
            arow[g][k] = A[(size_t)(m0 + g) * DF + k];
    __syncthreads();

    if (tid < Ncols) {
        float bv = bias[tid];
        float acc[8];
        #pragma unroll
        for (int g = 0; g < 8; g++) acc[g] = bv;
        for (int k = 0; k < DF; k += 4) {
            float w0 = Wt[(size_t)(k + 0) * Ncols + tid];
            float w1 = Wt[(size_t)(k + 1) * Ncols + tid];
            float w2 = Wt[(size_t)(k + 2) * Ncols + tid];
            float w3 = Wt[(size_t)(k + 3) * Ncols + tid];
            #pragma unroll
            for (int g = 0; g < 8; g++) {
                float4 av = *(const float4*)&arow[g][k];
                acc[g] += av.x * w0 + av.y * w1 + av.z * w2 + av.w * w3;
            }
        }
        #pragma unroll
        for (int g = 0; g < 8; g++) {
            float v = acc[g];
            if (act) v = 1.f / (1.f + expf(-v));
            out[(size_t)(m0 + g) * Ncols + tid] = v;
        }
    }
}

// ---------------- launch ----------------
extern "C" void kernel_launch(void* const* d_in, const int* in_sizes, int n_in,
                              void* d_out, int out_size) {
    const float* data = (const float*)d_in[0];
    const float* rois = (const float*)d_in[1];
    const float* w1   = (const float*)d_in[2];
    const float* b1   = (const float*)d_in[3];
    const float* w2   = (const float*)d_in[4];
    const float* b2   = (const float*)d_in[5];
    const float* w3   = (const float*)d_in[6];
    const float* b3   = (const float*)d_in[7];
    const float* wm1  = (const float*)d_in[8];
    const float* bm1  = (const float*)d_in[9];
    const float* wm2  = (const float*)d_in[10];
    const float* bm2  = (const float*)d_in[11];
    float* out = (float*)d_out;

    float *p_part, *p_m1, *p_h2, *p_off, *p_mask;
    __nv_bfloat16 *p_xh, *p_xl, *p_W1h, *p_W1l, *p_W2h, *p_W2l, *p_h1h, *p_h1l;
    cudaGetSymbolAddress((void**)&p_part, g_part);
    cudaGetSymbolAddress((void**)&p_m1,   g_m1);
    cudaGetSymbolAddress((void**)&p_h2,   g_h2);
    cudaGetSymbolAddress((void**)&p_off,  g_off);
    cudaGetSymbolAddress((void**)&p_mask, g_mask);
    cudaGetSymbolAddress((void**)&p_xh,   g_xh);
    cudaGetSymbolAddress((void**)&p_xl,   g_xl);
    cudaGetSymbolAddress((void**)&p_W1h,  g_Wt1h);
    cudaGetSymbolAddress((void**)&p_W1l,  g_Wt1l);
    cudaGetSymbolAddress((void**)&p_W2h,  g_Wt2h);
    cudaGetSymbolAddress((void**)&p_W2l,  g_Wt2l);
    cudaGetSymbolAddress((void**)&p_h1h,  g_h1h);
    cudaGetSymbolAddress((void**)&p_h1l,  g_h1l);

    static int attr_set = 0;
    if (!attr_set) {
        cudaFuncSetAttribute(gemm_wmma, cudaFuncAttributeMaxDynamicSharedMemorySize,
                             NSTG * STG_ELEMS * 2);
        attr_set = 1;
    }
    const int smem_bytes = NSTG * STG_ELEMS * 2;   // 73728

    // idx 0: transpose data to channel-last
    transpose_kernel<<<dim3(HW/32, Cc/32, Bb), dim3(32, 8)>>>(data);

    // idx 1: weight transpose + split for w1 & wm1 (merged)
    transW_kernel<<<dim3(INF/32, DF/32, 2), dim3(32, 8)>>>(w1, wm1, p_W1h, p_W1l, INF, 1);

    // idx 2: pool1 -> xh/xl bf16
    pool_kernel<false><<<dim3(Nroi*Pn/4), 128>>>(rois, nullptr, nullptr, nullptr);

    // idx 3 (ncu capture slot): gemm1 [256x6272]@[6272x2048], 3 terms x splitK7 -> 21 slices, 672 CTAs
    gemm_wmma<<<dim3(16, 2, 21), 256, smem_bytes>>>(p_xh, p_xl, INF, p_W1h, p_W1l, INF,
                                                    p_part, INF/7, 7, 2*DF);

    // idx 4: weight transpose + split for w2
    transW_kernel<<<dim3(DF/32, DF/32, 1), dim3(32, 8)>>>(w2, nullptr, p_W2h, p_W2l, DF, 0);

    // idx 5: reduce -> h1 (bf16 hi/lo) and m1 (fp32)
    reduce1_kernel<<<(Nroi*2*DF)/256, 256>>>(b1, bm1);

    // idx 6: gemm2 [256x1024]@[1024x1024], 3 terms x splitK8 -> 24 slices, 384 CTAs
    gemm_wmma<<<dim3(8, 2, 24), 256, smem_bytes>>>(p_h1h, p_h1l, DF, p_W2h, p_W2l, DF,
                                                   p_part, DF/8, 8, DF);

    // idx 7: reduce -> h2 fp32
    reduce2_kernel<<<(Nroi*DF)/256, 256>>>(b2);

    // idx 8/9: offsets & mask heads
    gemm_small<<<Nroi/8, 128>>>(p_h2, w3, b3, p_off, 2*Pn*Pn, 0);
    gemm_small<<<Nroi/8, 128>>>(p_m1, wm2, bm2, p_mask, Pn*Pn, 1);

    // idx 10: pool2 with offsets, multiply mask -> out
    pool_kernel<true><<<dim3(Nroi*Pn/4), 128>>>(rois, p_off, p_mask, out);
}

// round 13
// speedup vs baseline: 1.1804x; 1.1261x over previous
#include <cuda_runtime.h>
#include <cuda_bf16.h>
#include <mma.h>
#include <math.h>
#include <stdint.h>

using namespace nvcuda;

#define Pn 7
#define Sn 4
#define SCALE 0.0625f
#define TRANS_STD 0.1f
#define Cc 128
#define DF 1024
#define Bb 2
#define Hh 160
#define Ww 160
#define Nroi 256
#define INF (Cc*Pn*Pn)   // 6272
#define HW (Hh*Ww)       // 25600

// ---------------- scratch ----------------
__device__ float g_dataT[Bb*HW*Cc];                 // (B,H,W,C)
__device__ __align__(16) __nv_bfloat16 g_xh[Nroi*INF];
__device__ __align__(16) __nv_bfloat16 g_xl[Nroi*INF];
__device__ __align__(16) __nv_bfloat16 g_Wt1h[2*DF*INF];   // [2048][6272] = w1^T | wm1^T (hi)
__device__ __align__(16) __nv_bfloat16 g_Wt1l[2*DF*INF];   // lo
__device__ __align__(16) __nv_bfloat16 g_Wt2h[DF*DF];      // w2^T hi
__device__ __align__(16) __nv_bfloat16 g_Wt2l[DF*DF];      // w2^T lo
__device__ float g_part[11010048];                  // partials (21*256*2048)
__device__ __align__(16) __nv_bfloat16 g_h1h[Nroi*DF];
__device__ __align__(16) __nv_bfloat16 g_h1l[Nroi*DF];
__device__ float g_m1[Nroi*DF];
__device__ float g_h2[Nroi*DF];
__device__ float g_off[Nroi*2*Pn*Pn];
__device__ float g_mask[Nroi*Pn*Pn];

__device__ __forceinline__ uint32_t smem_u32(const void* p) {
    uint32_t a;
    asm("{ .reg .u64 t; cvta.to.shared.u64 t, %1; cvt.u32.u64 %0, t; }" : "=r"(a) : "l"(p));
    return a;
}

// ---------------- transpose (B,C,H,W) -> (B,H,W,C) ----------------
__global__ void transpose_kernel(const float* __restrict__ in) {
    __shared__ float tile[32][33];
    int b  = blockIdx.z;
    int p0 = blockIdx.x * 32;
    int c0 = blockIdx.y * 32;
    int tx = threadIdx.x, ty = threadIdx.y;
    const float* src = in + (size_t)b * Cc * HW;
    float* dst = g_dataT + (size_t)b * HW * Cc;
    #pragma unroll
    for (int i = 0; i < 4; i++)
        tile[ty + 8*i][tx] = src[(c0 + ty + 8*i) * HW + p0 + tx];
    __syncthreads();
    #pragma unroll
    for (int i = 0; i < 4; i++)
        dst[(p0 + ty + 8*i) * Cc + c0 + tx] = tile[tx][ty + 8*i];
}

// ---------------- weight transpose + bf16 hi/lo split ----------------
__global__ void transW_kernel(const float* __restrict__ w_a, const float* __restrict__ w_b,
                              __nv_bfloat16* __restrict__ Wth,
                              __nv_bfloat16* __restrict__ Wtl,
                              int ldt, int two) {
    __shared__ float tile[32][33];
    const float* w = (two && blockIdx.z) ? w_b : w_a;
    int nOff = (two && blockIdx.z) ? DF : 0;
    int k0 = blockIdx.x * 32;
    int n0 = blockIdx.y * 32;
    int tx = threadIdx.x, ty = threadIdx.y;
    #pragma unroll
    for (int i = 0; i < 4; i++)
        tile[ty + 8*i][tx] = w[(size_t)(k0 + ty + 8*i) * DF + n0 + tx];
    __syncthreads();
    #pragma unroll
    for (int i = 0; i < 4; i++) {
        float v = tile[tx][ty + 8*i];
        __nv_bfloat16 hi = __float2bfloat16(v);
        __nv_bfloat16 lo = __float2bfloat16(v - __bfloat162float(hi));
        size_t o = (size_t)(nOff + n0 + ty + 8*i) * ldt + k0 + tx;
        Wth[o] = hi;
        Wtl[o] = lo;
    }
}

// ---------------- deformable RoI pool (two-phase hybrid) ----------------
// grid (Nroi, Pn), 128 threads.
// Phase 1: threads 0..111 compute sample descriptors (one per pw x sub-sample).
// Phase 2: warp w handles pw in {w, w+4}; lane l covers channels 4l..4l+3 (float4).
template<bool TRANS>
__global__ __launch_bounds__(128) void pool_kernel(
    const float* __restrict__ rois,
    const float* __restrict__ trans,
    const float* __restrict__ mask,
    float* __restrict__ out)
{
    __shared__ int4   s_o[Pn*16];
    __shared__ float4 s_w[Pn*16];
    __shared__ int    s_cnt[Pn];
    __shared__ int    s_base;

    int n  = blockIdx.x;
    int ph = blockIdx.y;
    int tid = threadIdx.x;

    if (tid < Pn) s_cnt[tid] = 0;
    __syncthreads();

    if (tid < Pn * 16) {
        int pw = tid >> 4;
        int s  = tid & 15;
        int ih = s >> 2;
        int iw = s & 3;

        const float* r = rois + n * 5;
        int   bi = (int)r[0];
        float x1 = rintf(r[1]) * SCALE - 0.5f;
        float y1 = rintf(r[2]) * SCALE - 0.5f;
        float x2 = (rintf(r[3]) + 1.0f) * SCALE - 0.5f;
        float y2 = (rintf(r[4]) + 1.0f) * SCALE - 0.5f;
        float roi_w = fmaxf(x2 - x1, 0.1f);
        float roi_h = fmaxf(y2 - y1, 0.1f);
        float bin_w = roi_w / (float)Pn;
        float bin_h = roi_h / (float)Pn;
        float sub_w = bin_w / (float)Sn;
        float sub_h = bin_h / (float)Sn;

        float tx = 0.f, tyv = 0.f;
        if (TRANS) {
            tx  = trans[n*98 +      ph*7 + pw] * TRANS_STD;
            tyv = trans[n*98 + 49 + ph*7 + pw] * TRANS_STD;
        }
        float wv = (float)pw * bin_w + x1 + tx  * roi_w + (float)iw * sub_w;
        float hv = (float)ph * bin_h + y1 + tyv * roi_h + (float)ih * sub_h;

        int4   o4 = make_int4(0, 0, 0, 0);
        float4 w4 = make_float4(0.f, 0.f, 0.f, 0.f);
        bool valid = !(wv < -0.5f || wv > (float)Ww - 0.5f ||
                       hv < -0.5f || hv > (float)Hh - 0.5f);
        if (valid) {
            float wc = fminf(fmaxf(wv, 0.f), (float)Ww - 1.f);
            float hc = fminf(fmaxf(hv, 0.f), (float)Hh - 1.f);
            int x0 = (int)floorf(wc);
            int y0 = (int)floorf(hc);
            int x1i = min(x0 + 1, Ww - 1);
            int y1i = min(y0 + 1, Hh - 1);
            float lx = wc - (float)x0;
            float ly = hc - (float)y0;
            o4.x = (y0 * Ww + x0) * Cc;
            o4.y = (x1i - x0) * Cc;
            o4.z = (y1i - y0) * Ww * Cc;
            w4 = make_float4((1.f-ly)*(1.f-lx), (1.f-ly)*lx, ly*(1.f-lx), ly*lx);
            atomicAdd(&s_cnt[pw], 1);
        }
        s_o[tid] = o4;
        s_w[tid] = w4;
        if (tid == 0) s_base = bi * HW * Cc;
    }
    __syncthreads();

    int wid = tid >> 5;
    int l   = tid & 31;
    const float* base = g_dataT + s_base;
    int c4 = l * 4;

    #pragma unroll
    for (int pp = 0; pp < 2; pp++) {
        int pw = wid + pp * 4;
        if (pw >= Pn) break;
        float4 acc = make_float4(0.f, 0.f, 0.f, 0.f);
        #pragma unroll 4
        for (int s = 0; s < 16; s++) {
            int4   o = s_o[pw*16 + s];
            float4 w = s_w[pw*16 + s];
            const float* p = base + o.x + c4;
            float4 v00 = *(const float4*)(p);
            float4 v01 = *(const float4*)(p + o.y);
            float4 v10 = *(const float4*)(p + o.z);
            float4 v11 = *(const float4*)(p + o.y + o.z);
            acc.x += v00.x*w.x + v01.x*w.y + v10.x*w.z + v11.x*w.w;
            acc.y += v00.y*w.x + v01.y*w.y + v10.y*w.z + v11.y*w.w;
            acc.z += v00.z*w.x + v01.z*w.y + v10.z*w.z + v11.z*w.w;
            acc.w += v00.w*w.x + v01.w*w.y + v10.w*w.z + v11.w*w.w;
        }
        int cnt = s_cnt[pw];
        float a[4] = {acc.x, acc.y, acc.z, acc.w};
        float mk = TRANS ? mask[n*49 + ph*7 + pw] : 0.f;
        #pragma unroll
        for (int j = 0; j < 4; j++) {
            float res = (cnt > 0) ? a[j] / (float)cnt : 0.f;
            int oidx = n*INF + (c4 + j)*49 + ph*7 + pw;
            if (TRANS) {
                out[oidx] = res * mk;
            } else {
                __nv_bfloat16 hi = __float2bfloat16(res);
                g_xh[oidx] = hi;
                g_xl[oidx] = __float2bfloat16(res - __bfloat162float(hi));
            }
        }
    }
}

// ---------------- WMMA bf16 GEMM, cp.async 2-stage, KS=64 ----------------
// grid: x = Ntiles, y = Mtiles, z = term*kchunks + kc
//   term 0: Ah@Bh   term 1: Ah@Bl   term 2: Al@Bh
#define KS 64
#define SPAD 72
#define NSTG 2
#define STG_ELEMS (2 * 128 * SPAD)     // A + B per stage (bf16 elems)
__global__ __launch_bounds__(256) void gemm_wmma(
    const __nv_bfloat16* __restrict__ Ah, const __nv_bfloat16* __restrict__ Al, int lda,
    const __nv_bfloat16* __restrict__ Bh, const __nv_bfloat16* __restrict__ Bl, int ldb,
    float* __restrict__ part, int Kper, int kchunks, int Nfull)
{
    extern __shared__ __nv_bfloat16 smem[];

    int tid = threadIdx.x;
    int wid = tid >> 5;
    int wm = wid & 3;       // 0..3 : M position (32 rows each)
    int wn = wid >> 2;      // 0..1 : N position (64 cols each)

    int z = blockIdx.z;
    int term = z / kchunks;
    int kc   = z % kchunks;
    const __nv_bfloat16* A = (term == 2) ? Al : Ah;
    const __nv_bfloat16* B = (term == 1) ? Bl : Bh;

    int m0 = blockIdx.y * 128;
    int n0 = blockIdx.x * 128;
    const __nv_bfloat16* Abase = A + (size_t)m0 * lda + (size_t)kc * Kper;
    const __nv_bfloat16* Bbase = B + (size_t)n0 * ldb + (size_t)kc * Kper;

    wmma::fragment<wmma::accumulator, 16, 16, 16, float> acc[2][4];
    #pragma unroll
    for (int i = 0; i < 2; i++)
        #pragma unroll
        for (int j = 0; j < 4; j++) wmma::fill_fragment(acc[i][j], 0.0f);

    int stages = Kper / KS;
    int r  = tid >> 3;       // row group
    int ch = tid & 7;        // 16B chunk within 128B row

    auto issue = [&](int s) {
        int buf = s % NSTG;
        __nv_bfloat16* dA = smem + buf * STG_ELEMS;
        __nv_bfloat16* dB = dA + 128 * SPAD;
        const __nv_bfloat16* a = Abase + s * KS;
        const __nv_bfloat16* b = Bbase + s * KS;
        #pragma unroll
        for (int i = 0; i < 4; i++) {
            int rr = i * 32 + r;
            uint32_t da = smem_u32(dA + rr * SPAD + ch * 8);
            asm volatile("cp.async.cg.shared.global [%0], [%1], 16;"
                         :: "r"(da), "l"(a + (size_t)rr * lda + ch * 8));
            uint32_t db = smem_u32(dB + rr * SPAD + ch * 8);
            asm volatile("cp.async.cg.shared.global [%0], [%1], 16;"
                         :: "r"(db), "l"(b + (size_t)rr * ldb + ch * 8));
        }
        asm volatile("cp.async.commit_group;");
    };

    #pragma unroll
    for (int i = 0; i < NSTG - 1; i++) {
        if (i < stages) issue(i);
        else asm volatile("cp.async.commit_group;");
    }

    for (int s = 0; s < stages; s++) {
        if (s + NSTG - 1 < stages) issue(s + NSTG - 1);
        else asm volatile("cp.async.commit_group;");

        asm volatile("cp.async.wait_group %0;" :: "n"(NSTG - 1));
        __syncthreads();

        int buf = s % NSTG;
        const __nv_bfloat16* cA = smem + buf * STG_ELEMS;
        const __nv_bfloat16* cB = cA + 128 * SPAD;
        #pragma unroll
        for (int kk = 0; kk < KS; kk += 16) {
            wmma::fragment<wmma::matrix_a, 16, 16, 16, __nv_bfloat16, wmma::row_major> af[2];
            wmma::fragment<wmma::matrix_b, 16, 16, 16, __nv_bfloat16, wmma::col_major> bfr[4];
            #pragma unroll
            for (int i = 0; i < 2; i++)
                wmma::load_matrix_sync(af[i], cA + (wm * 32 + i * 16) * SPAD + kk, SPAD);
            #pragma unroll
            for (int j = 0; j < 4; j++)
                wmma::load_matrix_sync(bfr[j], cB + (wn * 64 + j * 16) * SPAD + kk, SPAD);
            #pragma unroll
            for (int i = 0; i < 2; i++)
                #pragma unroll
                for (int j = 0; j < 4; j++)
                    wmma::mma_sync(acc[i][j], af[i], bfr[j], acc[i][j]);
        }
        __syncthreads();
    }

    float* outp = part + ((size_t)z * Nroi + m0) * Nfull + n0;
    #pragma unroll
    for (int i = 0; i < 2; i++)
        #pragma unroll
        for (int j = 0; j < 4; j++)
            wmma::store_matrix_sync(outp + (size_t)(wm * 32 + i * 16) * Nfull + wn * 64 + j * 16,
                                    acc[i][j], Nfull, wmma::mem_row_major);
}

// ---------------- reduce 1: sum 21 slices [256][2048]; split h (bf16 hi/lo) / m (fp32)
__global__ void reduce1_kernel(const float* __restrict__ b1, const float* __restrict__ bm1) {
    int i = blockIdx.x * 256 + threadIdx.x;   // over 256*2048
    int m = i >> 11;
    int n = i & 2047;
    float s = (n < DF) ? b1[n] : bm1[n - DF];
    #pragma unroll
    for (int zz = 0; zz < 21; zz++) s += g_part[(size_t)zz * (Nroi*2*DF) + i];
    s = fmaxf(s, 0.f);
    if (n < DF) {
        __nv_bfloat16 hi = __float2bfloat16(s);
        g_h1h[m*DF + n] = hi;
        g_h1l[m*DF + n] = __float2bfloat16(s - __bfloat162float(hi));
    } else {
        g_m1[m*DF + n - DF] = s;
    }
}

// ---------------- reduce 2: sum 24 slices [256][1024] + b2, relu -> h2 fp32
__global__ void reduce2_kernel(const float* __restrict__ b2) {
    int i = blockIdx.x * 256 + threadIdx.x;
    int n = i & (DF - 1);
    float s = b2[n];
    #pragma unroll
    for (int zz = 0; zz < 24; zz++) s += g_part[(size_t)zz * (Nroi*DF) + i];
    g_h2[i] = fmaxf(s, 0.f);
}

// ---------------- small GEMM: (256,1024) @ (1024,Ncols) + bias [, sigmoid] -------
__global__ __launch_bounds__(128) void gemm_small(
    const float* __restrict__ A, const float* __restrict__ Wt,
    const float* __restrict__ bias, float* __restrict__ out,
    int Ncols, int act)
{
    __shared__ float arow[8][DF];
    int tid = threadIdx.x;
    int m0 = blockIdx.x * 8;
    #pragma unroll
    for (int g = 0; g < 8; g++)
        for (int k = tid; k < DF; k += 128)
            arow[g][k] = A[(size_t)(m0 + g) * DF + k];
    __syncthreads();

    if (tid < Ncols) {
        float bv = bias[tid];
        float acc[8];
        #pragma unroll
        for (int g = 0; g < 8; g++) acc[g] = bv;
        for (int k = 0; k < DF; k += 4) {
            float w0 = Wt[(size_t)(k + 0) * Ncols + tid];
            float w1 = Wt[(size_t)(k + 1) * Ncols + tid];
            float w2 = Wt[(size_t)(k + 2) * Ncols + tid];
            float w3 = Wt[(size_t)(k + 3) * Ncols + tid];
            #pragma unroll
            for (int g = 0; g < 8; g++) {
                float4 av = *(const float4*)&arow[g][k];
                acc[g] += av.x * w0 + av.y * w1 + av.z * w2 + av.w * w3;
            }
        }
        #pragma unroll
        for (int g = 0; g < 8; g++) {
            float v = acc[g];
            if (act) v = 1.f / (1.f + expf(-v));
            out[(size_t)(m0 + g) * Ncols + tid] = v;
        }
    }
}

// ---------------- launch ----------------
extern "C" void kernel_launch(void* const* d_in, const int* in_sizes, int n_in,
                              void* d_out, int out_size) {
    const float* data = (const float*)d_in[0];
    const float* rois = (const float*)d_in[1];
    const float* w1   = (const float*)d_in[2];
    const float* b1   = (const float*)d_in[3];
    const float* w2   = (const float*)d_in[4];
    const float* b2   = (const float*)d_in[5];
    const float* w3   = (const float*)d_in[6];
    const float* b3   = (const float*)d_in[7];
    const float* wm1  = (const float*)d_in[8];
    const float* bm1  = (const float*)d_in[9];
    const float* wm2  = (const float*)d_in[10];
    const float* bm2  = (const float*)d_in[11];
    float* out = (float*)d_out;

    float *p_part, *p_m1, *p_h2, *p_off, *p_mask;
    __nv_bfloat16 *p_xh, *p_xl, *p_W1h, *p_W1l, *p_W2h, *p_W2l, *p_h1h, *p_h1l;
    cudaGetSymbolAddress((void**)&p_part, g_part);
    cudaGetSymbolAddress((void**)&p_m1,   g_m1);
    cudaGetSymbolAddress((void**)&p_h2,   g_h2);
    cudaGetSymbolAddress((void**)&p_off,  g_off);
    cudaGetSymbolAddress((void**)&p_mask, g_mask);
    cudaGetSymbolAddress((void**)&p_xh,   g_xh);
    cudaGetSymbolAddress((void**)&p_xl,   g_xl);
    cudaGetSymbolAddress((void**)&p_W1h,  g_Wt1h);
    cudaGetSymbolAddress((void**)&p_W1l,  g_Wt1l);
    cudaGetSymbolAddress((void**)&p_W2h,  g_Wt2h);
    cudaGetSymbolAddress((void**)&p_W2l,  g_Wt2l);
    cudaGetSymbolAddress((void**)&p_h1h,  g_h1h);
    cudaGetSymbolAddress((void**)&p_h1l,  g_h1l);

    static int attr_set = 0;
    if (!attr_set) {
        cudaFuncSetAttribute(gemm_wmma, cudaFuncAttributeMaxDynamicSharedMemorySize,
                             NSTG * STG_ELEMS * 2);
        attr_set = 1;
    }
    const int smem_bytes = NSTG * STG_ELEMS * 2;   // 73728

    // idx 0: transpose data to channel-last
    transpose_kernel<<<dim3(HW/32, Cc/32, Bb), dim3(32, 8)>>>(data);

    // idx 1: weight transpose + split for w1 & wm1 (merged)
    transW_kernel<<<dim3(INF/32, DF/32, 2), dim3(32, 8)>>>(w1, wm1, p_W1h, p_W1l, INF, 1);

    // idx 2: weight transpose + split for w2
    transW_kernel<<<dim3(DF/32, DF/32, 1), dim3(32, 8)>>>(w2, nullptr, p_W2h, p_W2l, DF, 0);

    // idx 3 (ncu capture slot): pool1 -> xh/xl bf16
    pool_kernel<false><<<dim3(Nroi, Pn), 128>>>(rois, nullptr, nullptr, nullptr);

    // idx 4: gemm1 [256x6272]@[6272x2048], 3 terms x splitK7 -> 21 slices, 672 CTAs
    gemm_wmma<<<dim3(16, 2, 21), 256, smem_bytes>>>(p_xh, p_xl, INF, p_W1h, p_W1l, INF,
                                                    p_part, INF/7, 7, 2*DF);

    // idx 5: reduce -> h1 (bf16 hi/lo) and m1 (fp32)
    reduce1_kernel<<<(Nroi*2*DF)/256, 256>>>(b1, bm1);

    // idx 6: gemm2 [256x1024]@[1024x1024], 3 terms x splitK8 -> 24 slices, 384 CTAs
    gemm_wmma<<<dim3(8, 2, 24), 256, smem_bytes>>>(p_h1h, p_h1l, DF, p_W2h, p_W2l, DF,
                                                   p_part, DF/8, 8, DF);

    // idx 7: reduce -> h2 fp32
    reduce2_kernel<<<(Nroi*DF)/256, 256>>>(b2);

    // idx 8/9: offsets & mask heads
    gemm_small<<<Nroi/8, 128>>>(p_h2, w3, b3, p_off, 2*Pn*Pn, 0);
    gemm_small<<<Nroi/8, 128>>>(p_m1, wm2, bm2, p_mask, Pn*Pn, 1);

    // idx 10: pool2 with offsets, multiply mask -> out
    pool_kernel<true><<<dim3(Nroi, Pn), 128>>>(rois, p_off, p_mask, out);
}